// round 11
// baseline (speedup 1.0000x reference)
#include <cuda_runtime.h>
#include <cstdint>

// Problem shape (fixed by reference)
static constexpr int B_ = 8, M_ = 4096, N_ = 1024, D_ = 1024;
static constexpr int ROWS = B_ * M_;            // 32768 LN rows
static constexpr int TM = 128, TN = 256;        // CTA tile (new: TN=256)
static constexpr int KC = 32;                   // K per chunk
static constexpr int NCHUNK = N_ / KC;          // 32
static constexpr int RB = ROWS / TM;            // 256 row blocks
static constexpr int NB = D_ / TN;              // 4 col blocks

// Chunk sizes (tf32 words)
static constexpr int A_CHUNK_WORDS = TM * KC;   // 4096  (16 KB)
static constexpr int B_CHUNK_WORDS = KC * TN;   // 8192  (32 KB)
static constexpr int STAGE_BYTES = (A_CHUNK_WORDS + B_CHUNK_WORDS) * 4;  // 49152
static constexpr int NSTAGE = 4;
static constexpr int SMEM_DYN = NSTAGE * STAGE_BYTES;                    // 196608

// Device-global fragment scratch (no allocation APIs)
// A fragments: [rb 256][c 32][mt 8][ks 4][lane 32][reg 4]
__device__ uint32_t g_afrag[(size_t)RB * NCHUNK * A_CHUNK_WORDS];
// B fragments: [nb 4][c 32][nt 32][ksp 2][lane 32][4 words]
//   uint4 = { b(ks=2p, t), b(ks=2p, t+4), b(ks=2p+1, t), b(ks=2p+1, t+4) }
__device__ uint32_t g_bfrag[(size_t)NB * NCHUNK * B_CHUNK_WORDS];

// ---------------------------------------------------------------- helpers ---
__device__ __forceinline__ uint32_t f2tf32(float f) {
    uint32_t r;
    asm("cvt.rna.tf32.f32 %0, %1;" : "=r"(r) : "f"(f));
    return r;
}

__device__ __forceinline__ uint32_t smem_u32(const void* p) {
    uint32_t a;
    asm("{ .reg .u64 t; cvta.to.shared.u64 t, %1; cvt.u32.u64 %0, t; }" : "=r"(a) : "l"(p));
    return a;
}

__device__ __forceinline__ void mma_tf32(float* c, const uint32_t* a,
                                         uint32_t b0, uint32_t b1) {
    asm volatile(
        "mma.sync.aligned.m16n8k8.row.col.f32.tf32.tf32.f32 "
        "{%0,%1,%2,%3}, {%4,%5,%6,%7}, {%8,%9}, {%0,%1,%2,%3};"
        : "+f"(c[0]), "+f"(c[1]), "+f"(c[2]), "+f"(c[3])
        : "r"(a[0]), "r"(a[1]), "r"(a[2]), "r"(a[3]), "r"(b0), "r"(b1));
}

__device__ __forceinline__ void cpasync16(uint32_t smem_addr, const void* gptr) {
    asm volatile("cp.async.cg.shared.global [%0], [%1], 16;"
                 :: "r"(smem_addr), "l"(gptr) : "memory");
}
#define CP_COMMIT()  asm volatile("cp.async.commit_group;" ::: "memory")
#define CP_WAIT(n)   asm volatile("cp.async.wait_group %0;" :: "n"(n) : "memory")

#define LDS128(r0, r1, r2, r3, addr) \
    asm volatile("ld.shared.v4.b32 {%0,%1,%2,%3}, [%4];" \
                 : "=r"(r0), "=r"(r1), "=r"(r2), "=r"(r3) : "r"(addr))

// -------------------------------- fused stats + LN -> A-fragment kernel ----
// One block = one 16-row mtile. Stages the 16x1024 x-slab in SMEM (read x ONCE),
// computes per-row mean/rstd, then emits fragment-layout tf32 (coalesced uint4).
// Fragment mapping (HW-verified by the R5/R8 passing kernels):
//   reg0=(row g, k t) reg1=(row g+8, k t) reg2=(row g, k t+4) reg3=(row g+8, k t+4)
static constexpr int XS_STRIDE = 1032;   // floats per row (1024 + 8 pad)
__global__ void __launch_bounds__(256) ln_prep_kernel(
    const float* __restrict__ x, const float* __restrict__ gamma,
    const float* __restrict__ beta) {
    extern __shared__ float sprep[];          // [16][1032] x + [1024] g + [1024] b
    float* xs = sprep;
    float* sg = sprep + 16 * XS_STRIDE;
    float* sb = sg + 1024;
    __shared__ float smean[16], srstd[16];

    const int blk = blockIdx.x;               // 0..2047 ; rb=blk>>3, mt=blk&7
    const int tid = threadIdx.x, w = tid >> 5, lane = tid & 31;

    // phase 1: coalesced load of 16 rows + gamma/beta
    {
        const float4* x4 = reinterpret_cast<const float4*>(x) + (size_t)blk * 16 * 256;
#pragma unroll
        for (int i = 0; i < 16; i++) {
            const int idx = i * 256 + tid;
            const int row = idx >> 8, col4 = idx & 255;
            *reinterpret_cast<float4*>(xs + row * XS_STRIDE + col4 * 4) = x4[row * 256 + col4];
        }
        reinterpret_cast<float4*>(sg)[tid] = reinterpret_cast<const float4*>(gamma)[tid];
        reinterpret_cast<float4*>(sb)[tid] = reinterpret_cast<const float4*>(beta)[tid];
    }
    __syncthreads();

    // phase 2: per-row stats (warp w handles rows 2w, 2w+1)
#pragma unroll
    for (int rr = 0; rr < 2; rr++) {
        const int row = w * 2 + rr;
        float s = 0.f, ss = 0.f;
#pragma unroll
        for (int j = 0; j < 8; j++) {
            const float4 v = *reinterpret_cast<const float4*>(
                xs + row * XS_STRIDE + (lane + j * 32) * 4);
            s  += v.x + v.y + v.z + v.w;
            ss += v.x * v.x + v.y * v.y + v.z * v.z + v.w * v.w;
        }
#pragma unroll
        for (int o = 16; o > 0; o >>= 1) {
            s  += __shfl_xor_sync(0xffffffffu, s, o);
            ss += __shfl_xor_sync(0xffffffffu, ss, o);
        }
        if (lane == 0) {
            const float m = s * (1.0f / N_);
            smean[row] = m;
            srstd[row] = rsqrtf(ss * (1.0f / N_) - m * m + 1e-5f);
        }
    }
    __syncthreads();

    // phase 3: emit fragments (warp w covers 16 (c,ks) combos)
    const int g = lane >> 2, t = lane & 3;
    const float mn0 = smean[g],     rs0 = srstd[g];
    const float mn1 = smean[g + 8], rs1 = srstd[g + 8];
    const float* xr0 = xs + g * XS_STRIDE;
    const float* xr1 = xs + (g + 8) * XS_STRIDE;
    uint4* dst_base = reinterpret_cast<uint4*>(g_afrag) + ((size_t)blk * 128 + lane) ;
#pragma unroll
    for (int i = 0; i < 16; i++) {
        const int c  = (i >> 2) * 8 + w;
        const int ks = i & 3;
        const int k0 = c * KC + ks * 8 + t, k1 = k0 + 4;
        const float ga0 = sg[k0], be0 = sb[k0];
        const float ga1 = sg[k1], be1 = sb[k1];
        uint4 o;
        o.x = f2tf32((xr0[k0] - mn0) * rs0 * ga0 + be0);
        o.y = f2tf32((xr1[k0] - mn1) * rs1 * ga0 + be0);
        o.z = f2tf32((xr0[k1] - mn0) * rs0 * ga1 + be1);
        o.w = f2tf32((xr1[k1] - mn1) * rs1 * ga1 + be1);
        // g_afrag word index = ((rb*32 + c)*32 + mt*4 + ks)*128 + lane*4
        // blk*128 uint4 covers the mtile; within: (c*... ) reorganized:
        // global uint4 idx = ((rb*32+c)*32 + mt*4 + ks)*32 + lane
        const int rb = blk >> 3, mt = blk & 7;
        reinterpret_cast<uint4*>(g_afrag)[
            (((size_t)(rb * 32 + c) * 32) + mt * 4 + ks) * 32 + lane] = o;
    }
    (void)dst_base;
}

// --------------------------------------------- w -> tf32 B-fragment kernel ---
__global__ void __launch_bounds__(256) w_frag_kernel(const float* __restrict__ w) {
    const int c = blockIdx.x, nb = blockIdx.y;
    const int tid = threadIdx.x, wr = tid >> 5, lane = tid & 31;
    const int g = lane >> 2, t = lane & 3;
#pragma unroll
    for (int i = 0; i < 8; i++) {
        const int nt = wr * 4 + (i >> 1);
        const int ksp = i & 1;
        const int n = nb * TN + nt * 8 + g;
        const int kb = c * KC + ksp * 16 + t;
        uint4 o;
        o.x = f2tf32(w[(size_t)kb * D_ + n]);
        o.y = f2tf32(w[(size_t)(kb + 4) * D_ + n]);
        o.z = f2tf32(w[(size_t)(kb + 8) * D_ + n]);
        o.w = f2tf32(w[(size_t)(kb + 12) * D_ + n]);
        reinterpret_cast<uint4*>(g_bfrag)[
            ((size_t)(nb * NCHUNK + c) * 2048) + (nt * 2 + ksp) * 32 + lane] = o;
    }
}

// ------------------------------------------------------------- GEMM kernel ---
// CTA 128x256, 8 warps, warp tile 64x64 (wm=wid>>2 in {0,1}, wn=wid&3 in 0..3).
__global__ void __launch_bounds__(256, 1) ln_gemm_kernel(
    const float* __restrict__ bias, float* __restrict__ out) {
    extern __shared__ uint32_t smw[];
    const uint32_t sbase = smem_u32(smw);
    const int tid = threadIdx.x, wid = tid >> 5, lane = tid & 31;
    const int bx = blockIdx.x, by = blockIdx.y;
    const int wm = wid >> 2, wn = wid & 3;

    const uint4* gA = reinterpret_cast<const uint4*>(g_afrag) + (size_t)by * NCHUNK * 1024;
    const uint4* gB = reinterpret_cast<const uint4*>(g_bfrag) + (size_t)bx * NCHUNK * 2048;

    auto issue = [&](int chunk, int stage) {
        const uint32_t dstA = sbase + (uint32_t)stage * STAGE_BYTES + tid * 16;
        const uint4* srcA = gA + chunk * 1024 + tid;
#pragma unroll
        for (int i = 0; i < 4; i++) cpasync16(dstA + i * 4096, srcA + i * 256);
        const uint32_t dstB = dstA + A_CHUNK_WORDS * 4;
        const uint4* srcB = gB + chunk * 2048 + tid;
#pragma unroll
        for (int i = 0; i < 8; i++) cpasync16(dstB + i * 4096, srcB + i * 256);
        CP_COMMIT();
    };

    issue(0, 0);
    issue(1, 1);
    issue(2, 2);

    float acc[4][8][4];
#pragma unroll
    for (int i = 0; i < 4; i++)
#pragma unroll
        for (int j = 0; j < 8; j++)
#pragma unroll
            for (int r = 0; r < 4; r++) acc[i][j][r] = 0.f;

    for (int c = 0; c < NCHUNK; c++) {
        if (c < NCHUNK - 3)      { CP_WAIT(2); }
        else if (c == NCHUNK - 3){ CP_WAIT(2); }
        else if (c == NCHUNK - 2){ CP_WAIT(1); }
        else                     { CP_WAIT(0); }
        __syncthreads();
        if (c + 3 < NCHUNK) issue(c + 3, (c + 3) & 3);

        const uint32_t Asw = sbase + (uint32_t)(c & 3) * STAGE_BYTES;
        const uint32_t Bsw = Asw + A_CHUNK_WORDS * 4;

#pragma unroll
        for (int ksp = 0; ksp < 2; ksp++) {
            uint32_t bfr[8][4];
#pragma unroll
            for (int j = 0; j < 8; j++)
                LDS128(bfr[j][0], bfr[j][1], bfr[j][2], bfr[j][3],
                       Bsw + (uint32_t)((((wn * 8 + j) * 2 + ksp) * 128 + lane * 4) * 4));
#pragma unroll
            for (int h = 0; h < 2; h++) {
                const int ks = ksp * 2 + h;
                uint32_t afr[4][4];
#pragma unroll
                for (int i = 0; i < 4; i++)
                    LDS128(afr[i][0], afr[i][1], afr[i][2], afr[i][3],
                           Asw + (uint32_t)((((wm * 4 + i) * 4 + ks) * 128 + lane * 4) * 4));
#pragma unroll
                for (int i = 0; i < 4; i++)
#pragma unroll
                    for (int j = 0; j < 8; j++)
                        mma_tf32(acc[i][j], afr[i], bfr[j][2 * h], bfr[j][2 * h + 1]);
            }
        }
    }

    // ---- epilogue: acc + bias -> gmem
    const int d0 = bx * TN;
    const int row_base = by * TM;
    const int g = lane >> 2;
    const int t = lane & 3;
    float2 bb[8];
#pragma unroll
    for (int j = 0; j < 8; j++)
        bb[j] = *reinterpret_cast<const float2*>(bias + d0 + wn * 64 + j * 8 + 2 * t);
#pragma unroll
    for (int i = 0; i < 4; i++) {
        const int r0 = row_base + wm * 64 + i * 16 + g;
#pragma unroll
        for (int j = 0; j < 8; j++) {
            const int col = d0 + wn * 64 + j * 8 + 2 * t;
            float2 o0, o1;
            o0.x = acc[i][j][0] + bb[j].x;
            o0.y = acc[i][j][1] + bb[j].y;
            o1.x = acc[i][j][2] + bb[j].x;
            o1.y = acc[i][j][3] + bb[j].y;
            *reinterpret_cast<float2*>(out + (size_t)r0 * D_ + col) = o0;
            *reinterpret_cast<float2*>(out + (size_t)(r0 + 8) * D_ + col) = o1;
        }
    }
}

// ------------------------------------------------------------------ launch ---
extern "C" void kernel_launch(void* const* d_in, const int* in_sizes, int n_in,
                              void* d_out, int out_size) {
    const float* x     = (const float*)d_in[0];
    const float* w     = (const float*)d_in[1];
    const float* b     = (const float*)d_in[2];
    const float* gamma = (const float*)d_in[3];
    const float* beta  = (const float*)d_in[4];
    float* out = (float*)d_out;

    static constexpr int PREP_SMEM = (16 * XS_STRIDE + 2048) * 4;  // 74240 B
    cudaFuncSetAttribute(ln_prep_kernel, cudaFuncAttributeMaxDynamicSharedMemorySize, PREP_SMEM);
    cudaFuncSetAttribute(ln_gemm_kernel, cudaFuncAttributeMaxDynamicSharedMemorySize, SMEM_DYN);

    w_frag_kernel<<<dim3(NCHUNK, NB), 256>>>(w);
    ln_prep_kernel<<<ROWS / 16, 256, PREP_SMEM>>>(x, gamma, beta);
    ln_gemm_kernel<<<dim3(NB, RB), 256, SMEM_DYN>>>(b, out);
}

// round 12
// speedup vs baseline: 1.0184x; 1.0184x over previous
#include <cuda_runtime.h>
#include <cstdint>

// Problem shape (fixed by reference)
static constexpr int B_ = 8, M_ = 4096, N_ = 1024, D_ = 1024;
static constexpr int ROWS = B_ * M_;            // 32768 LN rows
static constexpr int TM = 128, TN = 256;        // CTA tile
static constexpr int KC = 32;                   // K per chunk
static constexpr int NCHUNK = N_ / KC;          // 32
static constexpr int RB = ROWS / TM;            // 256 row blocks
static constexpr int NB = D_ / TN;              // 4 col blocks

static constexpr int A_CHUNK_WORDS = TM * KC;   // 4096  (16 KB)
static constexpr int B_CHUNK_WORDS = KC * TN;   // 8192  (32 KB, gmem only now)
static constexpr int NSTAGE = 4;                // A-only stages
static constexpr int STAGE_BYTES = A_CHUNK_WORDS * 4;          // 16384
static constexpr int SMEM_DYN = NSTAGE * STAGE_BYTES;          // 65536

// Device-global fragment scratch (no allocation APIs)
// A fragments: [rb 256][c 32][mt 8][ks 4][lane 32][reg 4]
__device__ uint32_t g_afrag[(size_t)RB * NCHUNK * A_CHUNK_WORDS];
// B fragments: [nb 4][c 32][nt 32][ksp 2][lane 32][4 words]
//   uint4 = { b(ks=2p, t), b(ks=2p, t+4), b(ks=2p+1, t), b(ks=2p+1, t+4) }
__device__ uint32_t g_bfrag[(size_t)NB * NCHUNK * B_CHUNK_WORDS];

// ---------------------------------------------------------------- helpers ---
__device__ __forceinline__ uint32_t f2tf32(float f) {
    uint32_t r;
    asm("cvt.rna.tf32.f32 %0, %1;" : "=r"(r) : "f"(f));
    return r;
}

__device__ __forceinline__ uint32_t smem_u32(const void* p) {
    uint32_t a;
    asm("{ .reg .u64 t; cvta.to.shared.u64 t, %1; cvt.u32.u64 %0, t; }" : "=r"(a) : "l"(p));
    return a;
}

__device__ __forceinline__ void mma_tf32(float* c, const uint32_t* a,
                                         uint32_t b0, uint32_t b1) {
    asm volatile(
        "mma.sync.aligned.m16n8k8.row.col.f32.tf32.tf32.f32 "
        "{%0,%1,%2,%3}, {%4,%5,%6,%7}, {%8,%9}, {%0,%1,%2,%3};"
        : "+f"(c[0]), "+f"(c[1]), "+f"(c[2]), "+f"(c[3])
        : "r"(a[0]), "r"(a[1]), "r"(a[2]), "r"(a[3]), "r"(b0), "r"(b1));
}

__device__ __forceinline__ void cpasync16(uint32_t smem_addr, const void* gptr) {
    asm volatile("cp.async.cg.shared.global [%0], [%1], 16;"
                 :: "r"(smem_addr), "l"(gptr) : "memory");
}
#define CP_COMMIT()  asm volatile("cp.async.commit_group;" ::: "memory")
#define CP_WAIT(n)   asm volatile("cp.async.wait_group %0;" :: "n"(n) : "memory")

#define LDS128(r0, r1, r2, r3, addr) \
    asm volatile("ld.shared.v4.b32 {%0,%1,%2,%3}, [%4];" \
                 : "=r"(r0), "=r"(r1), "=r"(r2), "=r"(r3) : "r"(addr))

// -------------------------------- fused stats + LN -> A-fragment kernel ----
// (unchanged from the passing R11 kernel; HW-verified fragment layout)
static constexpr int XS_STRIDE = 1032;
__global__ void __launch_bounds__(256) ln_prep_kernel(
    const float* __restrict__ x, const float* __restrict__ gamma,
    const float* __restrict__ beta) {
    extern __shared__ float sprep[];
    float* xs = sprep;
    float* sg = sprep + 16 * XS_STRIDE;
    float* sb = sg + 1024;
    __shared__ float smean[16], srstd[16];

    const int blk = blockIdx.x;
    const int tid = threadIdx.x, w = tid >> 5, lane = tid & 31;

    {
        const float4* x4 = reinterpret_cast<const float4*>(x) + (size_t)blk * 16 * 256;
#pragma unroll
        for (int i = 0; i < 16; i++) {
            const int idx = i * 256 + tid;
            const int row = idx >> 8, col4 = idx & 255;
            *reinterpret_cast<float4*>(xs + row * XS_STRIDE + col4 * 4) = x4[row * 256 + col4];
        }
        reinterpret_cast<float4*>(sg)[tid] = reinterpret_cast<const float4*>(gamma)[tid];
        reinterpret_cast<float4*>(sb)[tid] = reinterpret_cast<const float4*>(beta)[tid];
    }
    __syncthreads();

#pragma unroll
    for (int rr = 0; rr < 2; rr++) {
        const int row = w * 2 + rr;
        float s = 0.f, ss = 0.f;
#pragma unroll
        for (int j = 0; j < 8; j++) {
            const float4 v = *reinterpret_cast<const float4*>(
                xs + row * XS_STRIDE + (lane + j * 32) * 4);
            s  += v.x + v.y + v.z + v.w;
            ss += v.x * v.x + v.y * v.y + v.z * v.z + v.w * v.w;
        }
#pragma unroll
        for (int o = 16; o > 0; o >>= 1) {
            s  += __shfl_xor_sync(0xffffffffu, s, o);
            ss += __shfl_xor_sync(0xffffffffu, ss, o);
        }
        if (lane == 0) {
            const float m = s * (1.0f / N_);
            smean[row] = m;
            srstd[row] = rsqrtf(ss * (1.0f / N_) - m * m + 1e-5f);
        }
    }
    __syncthreads();

    const int g = lane >> 2, t = lane & 3;
    const float mn0 = smean[g],     rs0 = srstd[g];
    const float mn1 = smean[g + 8], rs1 = srstd[g + 8];
    const float* xr0 = xs + g * XS_STRIDE;
    const float* xr1 = xs + (g + 8) * XS_STRIDE;
#pragma unroll
    for (int i = 0; i < 16; i++) {
        const int c  = (i >> 2) * 8 + w;
        const int ks = i & 3;
        const int k0 = c * KC + ks * 8 + t, k1 = k0 + 4;
        const float ga0 = sg[k0], be0 = sb[k0];
        const float ga1 = sg[k1], be1 = sb[k1];
        uint4 o;
        o.x = f2tf32((xr0[k0] - mn0) * rs0 * ga0 + be0);
        o.y = f2tf32((xr1[k0] - mn1) * rs1 * ga0 + be0);
        o.z = f2tf32((xr0[k1] - mn0) * rs0 * ga1 + be1);
        o.w = f2tf32((xr1[k1] - mn1) * rs1 * ga1 + be1);
        const int rb = blk >> 3, mt = blk & 7;
        reinterpret_cast<uint4*>(g_afrag)[
            (((size_t)(rb * 32 + c) * 32) + mt * 4 + ks) * 32 + lane] = o;
    }
}

// --------------------------------------------- w -> tf32 B-fragment kernel ---
__global__ void __launch_bounds__(256) w_frag_kernel(const float* __restrict__ w) {
    const int c = blockIdx.x, nb = blockIdx.y;
    const int tid = threadIdx.x, wr = tid >> 5, lane = tid & 31;
    const int g = lane >> 2, t = lane & 3;
#pragma unroll
    for (int i = 0; i < 8; i++) {
        const int nt = wr * 4 + (i >> 1);
        const int ksp = i & 1;
        const int n = nb * TN + nt * 8 + g;
        const int kb = c * KC + ksp * 16 + t;
        uint4 o;
        o.x = f2tf32(w[(size_t)kb * D_ + n]);
        o.y = f2tf32(w[(size_t)(kb + 4) * D_ + n]);
        o.z = f2tf32(w[(size_t)(kb + 8) * D_ + n]);
        o.w = f2tf32(w[(size_t)(kb + 12) * D_ + n]);
        reinterpret_cast<uint4*>(g_bfrag)[
            ((size_t)(nb * NCHUNK + c) * 2048) + (nt * 2 + ksp) * 32 + lane] = o;
    }
}

// ------------------------------------------------------------- GEMM kernel ---
// CTA 128x256, 8 warps, warp tile 64x64.
// A: cp.async -> SMEM (4 stages, 16KB each).  B: direct LDG.128 from L2 with
// one-ksp register lookahead (bA/bB ping-pong).
__global__ void __launch_bounds__(256, 1) ln_gemm_kernel(
    const float* __restrict__ bias, float* __restrict__ out) {
    extern __shared__ uint32_t smw[];
    const uint32_t sbase = smem_u32(smw);
    const int tid = threadIdx.x, wid = tid >> 5, lane = tid & 31;
    const int bx = blockIdx.x, by = blockIdx.y;
    const int wm = wid >> 2, wn = wid & 3;

    const uint4* gA = reinterpret_cast<const uint4*>(g_afrag) + (size_t)by * NCHUNK * 1024;
    // warp-specific B fragment base: fragments for (nt = wn*8 + j, ksp) at lane
    const uint4* gBw = reinterpret_cast<const uint4*>(g_bfrag)
                     + (size_t)bx * NCHUNK * 2048 + (wn * 8) * 2 * 32 + lane;

    auto issueA = [&](int chunk, int stage) {
        const uint32_t dstA = sbase + (uint32_t)stage * STAGE_BYTES + tid * 16;
        const uint4* srcA = gA + chunk * 1024 + tid;
#pragma unroll
        for (int i = 0; i < 4; i++) cpasync16(dstA + i * 4096, srcA + i * 256);
        CP_COMMIT();
    };

    // load this warp's 8 B-fragments for (chunk, ksp): j stride = 2*32 uint4
    auto ldgB = [&](int chunk, int ksp, uint4* dst) {
        const uint4* p = gBw + (size_t)chunk * 2048 + ksp * 32;
#pragma unroll
        for (int j = 0; j < 8; j++) dst[j] = p[j * 64];
    };

    issueA(0, 0);
    issueA(1, 1);
    issueA(2, 2);

    uint4 bA[8], bB[8];
    ldgB(0, 0, bA);

    float acc[4][8][4];
#pragma unroll
    for (int i = 0; i < 4; i++)
#pragma unroll
        for (int j = 0; j < 8; j++)
#pragma unroll
            for (int r = 0; r < 4; r++) acc[i][j][r] = 0.f;

    for (int c = 0; c < NCHUNK; c++) {
        if (c < NCHUNK - 2)       { CP_WAIT(2); }
        else if (c == NCHUNK - 2) { CP_WAIT(1); }
        else                      { CP_WAIT(0); }
        __syncthreads();
        if (c + 3 < NCHUNK) issueA(c + 3, (c + 3) & 3);

        const uint32_t Asw = sbase + (uint32_t)(c & 3) * STAGE_BYTES;

        // ---- ksp = 0: consume bA, prefetch (c,1) into bB
        ldgB(c, 1, bB);
#pragma unroll
        for (int h = 0; h < 2; h++) {
            const int ks = h;
            uint32_t afr[4][4];
#pragma unroll
            for (int i = 0; i < 4; i++)
                LDS128(afr[i][0], afr[i][1], afr[i][2], afr[i][3],
                       Asw + (uint32_t)((((wm * 4 + i) * 4 + ks) * 128 + lane * 4) * 4));
#pragma unroll
            for (int i = 0; i < 4; i++)
#pragma unroll
                for (int j = 0; j < 8; j++)
                    mma_tf32(acc[i][j], afr[i],
                             h ? bA[j].z : bA[j].x, h ? bA[j].w : bA[j].y);
        }

        // ---- ksp = 1: consume bB, prefetch (c+1,0) into bA
        if (c + 1 < NCHUNK) ldgB(c + 1, 0, bA);
#pragma unroll
        for (int h = 0; h < 2; h++) {
            const int ks = 2 + h;
            uint32_t afr[4][4];
#pragma unroll
            for (int i = 0; i < 4; i++)
                LDS128(afr[i][0], afr[i][1], afr[i][2], afr[i][3],
                       Asw + (uint32_t)((((wm * 4 + i) * 4 + ks) * 128 + lane * 4) * 4));
#pragma unroll
            for (int i = 0; i < 4; i++)
#pragma unroll
                for (int j = 0; j < 8; j++)
                    mma_tf32(acc[i][j], afr[i],
                             h ? bB[j].z : bB[j].x, h ? bB[j].w : bB[j].y);
        }
    }

    // ---- epilogue: acc + bias -> gmem
    const int d0 = bx * TN;
    const int row_base = by * TM;
    const int g = lane >> 2;
    const int t = lane & 3;
    float2 bb[8];
#pragma unroll
    for (int j = 0; j < 8; j++)
        bb[j] = *reinterpret_cast<const float2*>(bias + d0 + wn * 64 + j * 8 + 2 * t);
#pragma unroll
    for (int i = 0; i < 4; i++) {
        const int r0 = row_base + wm * 64 + i * 16 + g;
#pragma unroll
        for (int j = 0; j < 8; j++) {
            const int col = d0 + wn * 64 + j * 8 + 2 * t;
            float2 o0, o1;
            o0.x = acc[i][j][0] + bb[j].x;
            o0.y = acc[i][j][1] + bb[j].y;
            o1.x = acc[i][j][2] + bb[j].x;
            o1.y = acc[i][j][3] + bb[j].y;
            *reinterpret_cast<float2*>(out + (size_t)r0 * D_ + col) = o0;
            *reinterpret_cast<float2*>(out + (size_t)(r0 + 8) * D_ + col) = o1;
        }
    }
}

// ------------------------------------------------------------------ launch ---
extern "C" void kernel_launch(void* const* d_in, const int* in_sizes, int n_in,
                              void* d_out, int out_size) {
    const float* x     = (const float*)d_in[0];
    const float* w     = (const float*)d_in[1];
    const float* b     = (const float*)d_in[2];
    const float* gamma = (const float*)d_in[3];
    const float* beta  = (const float*)d_in[4];
    float* out = (float*)d_out;

    static constexpr int PREP_SMEM = (16 * XS_STRIDE + 2048) * 4;  // 74240 B
    cudaFuncSetAttribute(ln_prep_kernel, cudaFuncAttributeMaxDynamicSharedMemorySize, PREP_SMEM);
    cudaFuncSetAttribute(ln_gemm_kernel, cudaFuncAttributeMaxDynamicSharedMemorySize, SMEM_DYN);

    w_frag_kernel<<<dim3(NCHUNK, NB), 256>>>(w);
    ln_prep_kernel<<<ROWS / 16, 256, PREP_SMEM>>>(x, gamma, beta);
    ln_gemm_kernel<<<dim3(NB, RB), 256, SMEM_DYN>>>(b, out);
}

// round 13
// speedup vs baseline: 1.0337x; 1.0150x over previous
#include <cuda_runtime.h>
#include <cstdint>

// Problem shape (fixed by reference)
static constexpr int B_ = 8, M_ = 4096, N_ = 1024, D_ = 1024;
static constexpr int ROWS = B_ * M_;            // 32768 LN rows
static constexpr int TM = 128, TN = 256;        // CTA tile
static constexpr int KC = 32;                   // fragment-prep K granularity
static constexpr int NCHUNK = N_ / KC;          // 32 (prep layout)
static constexpr int RB = ROWS / TM;            // 256 row blocks
static constexpr int NB = D_ / TN;              // 4 col blocks

// GEMM mainloop K granularity (doubled: half the barriers)
static constexpr int KC2 = 64;
static constexpr int NCH2 = N_ / KC2;           // 16
static constexpr int A_CH2_WORDS = TM * KC2;    // 8192 (32 KB)
static constexpr int NSTAGE = 3;
static constexpr int STAGE_BYTES = A_CH2_WORDS * 4;            // 32768
static constexpr int SMEM_DYN = NSTAGE * STAGE_BYTES;          // 98304

static constexpr int A_CHUNK_WORDS = TM * KC;   // 4096 (prep layout unit)
static constexpr int B_CHUNK_WORDS = KC * TN;   // 8192

// Device-global fragment scratch (no allocation APIs)
// A fragments: [rb 256][c 32][mt 8][ks 4][lane 32][reg 4]
__device__ uint32_t g_afrag[(size_t)RB * NCHUNK * A_CHUNK_WORDS];
// B fragments: [nb 4][c 32][nt 32][ksp 2][lane 32][4 words]
//   uint4 = { b(ks=2p, t), b(ks=2p, t+4), b(ks=2p+1, t), b(ks=2p+1, t+4) }
__device__ uint32_t g_bfrag[(size_t)NB * NCHUNK * B_CHUNK_WORDS];

// ---------------------------------------------------------------- helpers ---
__device__ __forceinline__ uint32_t f2tf32(float f) {
    uint32_t r;
    asm("cvt.rna.tf32.f32 %0, %1;" : "=r"(r) : "f"(f));
    return r;
}

__device__ __forceinline__ uint32_t smem_u32(const void* p) {
    uint32_t a;
    asm("{ .reg .u64 t; cvta.to.shared.u64 t, %1; cvt.u32.u64 %0, t; }" : "=r"(a) : "l"(p));
    return a;
}

__device__ __forceinline__ void mma_tf32(float* c, const uint32_t* a,
                                         uint32_t b0, uint32_t b1) {
    asm volatile(
        "mma.sync.aligned.m16n8k8.row.col.f32.tf32.tf32.f32 "
        "{%0,%1,%2,%3}, {%4,%5,%6,%7}, {%8,%9}, {%0,%1,%2,%3};"
        : "+f"(c[0]), "+f"(c[1]), "+f"(c[2]), "+f"(c[3])
        : "r"(a[0]), "r"(a[1]), "r"(a[2]), "r"(a[3]), "r"(b0), "r"(b1));
}

__device__ __forceinline__ void cpasync16(uint32_t smem_addr, const void* gptr) {
    asm volatile("cp.async.cg.shared.global [%0], [%1], 16;"
                 :: "r"(smem_addr), "l"(gptr) : "memory");
}
#define CP_COMMIT()  asm volatile("cp.async.commit_group;" ::: "memory")
#define CP_WAIT(n)   asm volatile("cp.async.wait_group %0;" :: "n"(n) : "memory")

#define LDS128(r0, r1, r2, r3, addr) \
    asm volatile("ld.shared.v4.b32 {%0,%1,%2,%3}, [%4];" \
                 : "=r"(r0), "=r"(r1), "=r"(r2), "=r"(r3) : "r"(addr))

// -------------------------------- fused stats + LN -> A-fragment kernel ----
// (unchanged; HW-verified fragment layout)
static constexpr int XS_STRIDE = 1032;
__global__ void __launch_bounds__(256) ln_prep_kernel(
    const float* __restrict__ x, const float* __restrict__ gamma,
    const float* __restrict__ beta) {
    extern __shared__ float sprep[];
    float* xs = sprep;
    float* sg = sprep + 16 * XS_STRIDE;
    float* sb = sg + 1024;
    __shared__ float smean[16], srstd[16];

    const int blk = blockIdx.x;
    const int tid = threadIdx.x, w = tid >> 5, lane = tid & 31;

    {
        const float4* x4 = reinterpret_cast<const float4*>(x) + (size_t)blk * 16 * 256;
#pragma unroll
        for (int i = 0; i < 16; i++) {
            const int idx = i * 256 + tid;
            const int row = idx >> 8, col4 = idx & 255;
            *reinterpret_cast<float4*>(xs + row * XS_STRIDE + col4 * 4) = x4[row * 256 + col4];
        }
        reinterpret_cast<float4*>(sg)[tid] = reinterpret_cast<const float4*>(gamma)[tid];
        reinterpret_cast<float4*>(sb)[tid] = reinterpret_cast<const float4*>(beta)[tid];
    }
    __syncthreads();

#pragma unroll
    for (int rr = 0; rr < 2; rr++) {
        const int row = w * 2 + rr;
        float s = 0.f, ss = 0.f;
#pragma unroll
        for (int j = 0; j < 8; j++) {
            const float4 v = *reinterpret_cast<const float4*>(
                xs + row * XS_STRIDE + (lane + j * 32) * 4);
            s  += v.x + v.y + v.z + v.w;
            ss += v.x * v.x + v.y * v.y + v.z * v.z + v.w * v.w;
        }
#pragma unroll
        for (int o = 16; o > 0; o >>= 1) {
            s  += __shfl_xor_sync(0xffffffffu, s, o);
            ss += __shfl_xor_sync(0xffffffffu, ss, o);
        }
        if (lane == 0) {
            const float m = s * (1.0f / N_);
            smean[row] = m;
            srstd[row] = rsqrtf(ss * (1.0f / N_) - m * m + 1e-5f);
        }
    }
    __syncthreads();

    const int g = lane >> 2, t = lane & 3;
    const float mn0 = smean[g],     rs0 = srstd[g];
    const float mn1 = smean[g + 8], rs1 = srstd[g + 8];
    const float* xr0 = xs + g * XS_STRIDE;
    const float* xr1 = xs + (g + 8) * XS_STRIDE;
#pragma unroll
    for (int i = 0; i < 16; i++) {
        const int c  = (i >> 2) * 8 + w;
        const int ks = i & 3;
        const int k0 = c * KC + ks * 8 + t, k1 = k0 + 4;
        const float ga0 = sg[k0], be0 = sb[k0];
        const float ga1 = sg[k1], be1 = sb[k1];
        uint4 o;
        o.x = f2tf32((xr0[k0] - mn0) * rs0 * ga0 + be0);
        o.y = f2tf32((xr1[k0] - mn1) * rs1 * ga0 + be0);
        o.z = f2tf32((xr0[k1] - mn0) * rs0 * ga1 + be1);
        o.w = f2tf32((xr1[k1] - mn1) * rs1 * ga1 + be1);
        const int rb = blk >> 3, mt = blk & 7;
        reinterpret_cast<uint4*>(g_afrag)[
            (((size_t)(rb * 32 + c) * 32) + mt * 4 + ks) * 32 + lane] = o;
    }
}

// --------------------------------------------- w -> tf32 B-fragment kernel ---
__global__ void __launch_bounds__(256) w_frag_kernel(const float* __restrict__ w) {
    const int c = blockIdx.x, nb = blockIdx.y;
    const int tid = threadIdx.x, wr = tid >> 5, lane = tid & 31;
    const int g = lane >> 2, t = lane & 3;
#pragma unroll
    for (int i = 0; i < 8; i++) {
        const int nt = wr * 4 + (i >> 1);
        const int ksp = i & 1;
        const int n = nb * TN + nt * 8 + g;
        const int kb = c * KC + ksp * 16 + t;
        uint4 o;
        o.x = f2tf32(w[(size_t)kb * D_ + n]);
        o.y = f2tf32(w[(size_t)(kb + 4) * D_ + n]);
        o.z = f2tf32(w[(size_t)(kb + 8) * D_ + n]);
        o.w = f2tf32(w[(size_t)(kb + 12) * D_ + n]);
        reinterpret_cast<uint4*>(g_bfrag)[
            ((size_t)(nb * NCHUNK + c) * 2048) + (nt * 2 + ksp) * 32 + lane] = o;
    }
}

// ------------------------------------------------------------- GEMM kernel ---
// CTA 128x256, 8 warps, warp tile 64x64. K mainloop granularity 64 (one
// barrier per 64 K), A via cp.async 3-stage, B direct LDG.128 from L2 with
// one-slot register lookahead (4 ksp-slots per chunk, bX/bY ping-pong).
__global__ void __launch_bounds__(256, 1) ln_gemm_kernel(
    const float* __restrict__ bias, float* __restrict__ out) {
    extern __shared__ uint32_t smw[];
    const uint32_t sbase = smem_u32(smw);
    const int tid = threadIdx.x, wid = tid >> 5, lane = tid & 31;
    const int bx = blockIdx.x, by = blockIdx.y;
    const int wm = wid >> 2, wn = wid & 3;

    const uint4* gA = reinterpret_cast<const uint4*>(g_afrag) + (size_t)by * NCHUNK * 1024;
    const uint4* gBw = reinterpret_cast<const uint4*>(g_bfrag)
                     + (size_t)bx * NCHUNK * 2048 + (wn * 8) * 2 * 32 + lane;

    // one 64-K chunk = 32 KB of A fragments (two consecutive prep-chunks,
    // contiguous in g_afrag) -> 8 cp.async x 16B per thread
    auto issueA = [&](int c2, int stage) {
        const uint32_t dstA = sbase + (uint32_t)stage * STAGE_BYTES + tid * 16;
        const uint4* srcA = gA + c2 * 2048 + tid;
#pragma unroll
        for (int i = 0; i < 8; i++) cpasync16(dstA + i * 4096, srcA + i * 256);
        CP_COMMIT();
    };

    // this warp's 8 B-fragments for (prep-chunk c, ksp)
    auto ldgB = [&](int c, int ksp, uint4* dst) {
        const uint4* p = gBw + (size_t)c * 2048 + ksp * 32;
#pragma unroll
        for (int j = 0; j < 8; j++) dst[j] = p[j * 64];
    };

    issueA(0, 0);
    issueA(1, 1);

    uint4 bX[8], bY[8];
    ldgB(0, 0, bX);

    float acc[4][8][4];
#pragma unroll
    for (int i = 0; i < 4; i++)
#pragma unroll
        for (int j = 0; j < 8; j++)
#pragma unroll
            for (int r = 0; r < 4; r++) acc[i][j][r] = 0.f;

    for (int c2 = 0; c2 < NCH2; c2++) {
        if (c2 < NCH2 - 1) { CP_WAIT(1); } else { CP_WAIT(0); }
        __syncthreads();                       // everyone done reading stage (c2-1)%3
        if (c2 + 2 < NCH2) issueA(c2 + 2, (c2 + 2) % NSTAGE);

        const uint32_t Asw = sbase + (uint32_t)(c2 % NSTAGE) * STAGE_BYTES;

        // 4 ksp-slots: s -> (cc = s>>1, ksp = s&1), prep-chunk c = 2*c2+cc
#pragma unroll
        for (int s = 0; s < 4; s++) {
            uint4* cur = (s & 1) ? bY : bX;
            uint4* oth = (s & 1) ? bX : bY;
            // prefetch next slot (or next chunk's slot 0)
            if (s < 3)            ldgB(2 * c2 + ((s + 1) >> 1), (s + 1) & 1, oth);
            else if (c2 + 1 < NCH2) ldgB(2 * (c2 + 1), 0, oth);

            const int cc = s >> 1;
            const uint32_t Asub = Asw + (uint32_t)cc * 16384;
#pragma unroll
            for (int h = 0; h < 2; h++) {
                const int ks = (s & 1) * 2 + h;
                uint32_t afr[4][4];
#pragma unroll
                for (int i = 0; i < 4; i++)
                    LDS128(afr[i][0], afr[i][1], afr[i][2], afr[i][3],
                           Asub + (uint32_t)((((wm * 4 + i) * 4 + ks) * 128 + lane * 4) * 4));
#pragma unroll
                for (int i = 0; i < 4; i++)
#pragma unroll
                    for (int j = 0; j < 8; j++)
                        mma_tf32(acc[i][j], afr[i],
                                 h ? cur[j].z : cur[j].x, h ? cur[j].w : cur[j].y);
            }
        }
    }

    // ---- epilogue: acc + bias -> gmem
    const int d0 = bx * TN;
    const int row_base = by * TM;
    const int g = lane >> 2;
    const int t = lane & 3;
    float2 bb[8];
#pragma unroll
    for (int j = 0; j < 8; j++)
        bb[j] = *reinterpret_cast<const float2*>(bias + d0 + wn * 64 + j * 8 + 2 * t);
#pragma unroll
    for (int i = 0; i < 4; i++) {
        const int r0 = row_base + wm * 64 + i * 16 + g;
#pragma unroll
        for (int j = 0; j < 8; j++) {
            const int col = d0 + wn * 64 + j * 8 + 2 * t;
            float2 o0, o1;
            o0.x = acc[i][j][0] + bb[j].x;
            o0.y = acc[i][j][1] + bb[j].y;
            o1.x = acc[i][j][2] + bb[j].x;
            o1.y = acc[i][j][3] + bb[j].y;
            *reinterpret_cast<float2*>(out + (size_t)r0 * D_ + col) = o0;
            *reinterpret_cast<float2*>(out + (size_t)(r0 + 8) * D_ + col) = o1;
        }
    }
}

// ------------------------------------------------------------------ launch ---
extern "C" void kernel_launch(void* const* d_in, const int* in_sizes, int n_in,
                              void* d_out, int out_size) {
    const float* x     = (const float*)d_in[0];
    const float* w     = (const float*)d_in[1];
    const float* b     = (const float*)d_in[2];
    const float* gamma = (const float*)d_in[3];
    const float* beta  = (const float*)d_in[4];
    float* out = (float*)d_out;

    static constexpr int PREP_SMEM = (16 * XS_STRIDE + 2048) * 4;  // 74240 B
    cudaFuncSetAttribute(ln_prep_kernel, cudaFuncAttributeMaxDynamicSharedMemorySize, PREP_SMEM);
    cudaFuncSetAttribute(ln_gemm_kernel, cudaFuncAttributeMaxDynamicSharedMemorySize, SMEM_DYN);

    w_frag_kernel<<<dim3(NCHUNK, NB), 256>>>(w);
    ln_prep_kernel<<<ROWS / 16, 256, PREP_SMEM>>>(x, gamma, beta);
    ln_gemm_kernel<<<dim3(NB, RB), 256, SMEM_DYN>>>(b, out);
}

// round 14
// speedup vs baseline: 1.0566x; 1.0222x over previous
#include <cuda_runtime.h>
#include <cstdint>

// Problem shape (fixed by reference)
static constexpr int B_ = 8, M_ = 4096, N_ = 1024, D_ = 1024;
static constexpr int ROWS = B_ * M_;            // 32768 LN rows
static constexpr int TM = 128, TN = 256;        // CTA tile
static constexpr int KC = 32;                   // fragment-prep K granularity
static constexpr int NCHUNK = N_ / KC;          // 32 (prep layout)
static constexpr int RB = ROWS / TM;            // 256 row blocks
static constexpr int NB = D_ / TN;              // 4 col blocks

// GEMM mainloop K granularity
static constexpr int KC2 = 64;
static constexpr int NCH2 = N_ / KC2;           // 16
static constexpr int A_CH2_WORDS = TM * KC2;    // 8192 (32 KB)
static constexpr int NSTAGE = 3;
static constexpr int STAGE_BYTES = A_CH2_WORDS * 4;            // 32768
static constexpr int SMEM_DYN = NSTAGE * STAGE_BYTES;          // 98304

static constexpr int A_CHUNK_WORDS = TM * KC;   // 4096 (prep layout unit)
static constexpr int B_CHUNK_WORDS = KC * TN;   // 8192

// Device-global fragment scratch (no allocation APIs)
// A fragments: [rb 256][c 32][mt 8][ks 4][lane 32][reg 4]
__device__ uint32_t g_afrag[(size_t)RB * NCHUNK * A_CHUNK_WORDS];
// B fragments: [nb 4][c 32][nt 32][ksp 2][lane 32][4 words]
//   uint4 = { b(ks=2p, t), b(ks=2p, t+4), b(ks=2p+1, t), b(ks=2p+1, t+4) }
__device__ uint32_t g_bfrag[(size_t)NB * NCHUNK * B_CHUNK_WORDS];

// ---------------------------------------------------------------- helpers ---
__device__ __forceinline__ uint32_t f2tf32(float f) {
    uint32_t r;
    asm("cvt.rna.tf32.f32 %0, %1;" : "=r"(r) : "f"(f));
    return r;
}

__device__ __forceinline__ uint32_t smem_u32(const void* p) {
    uint32_t a;
    asm("{ .reg .u64 t; cvta.to.shared.u64 t, %1; cvt.u32.u64 %0, t; }" : "=r"(a) : "l"(p));
    return a;
}

__device__ __forceinline__ void mma_tf32(float* c, const uint32_t* a,
                                         uint32_t b0, uint32_t b1) {
    asm volatile(
        "mma.sync.aligned.m16n8k8.row.col.f32.tf32.tf32.f32 "
        "{%0,%1,%2,%3}, {%4,%5,%6,%7}, {%8,%9}, {%0,%1,%2,%3};"
        : "+f"(c[0]), "+f"(c[1]), "+f"(c[2]), "+f"(c[3])
        : "r"(a[0]), "r"(a[1]), "r"(a[2]), "r"(a[3]), "r"(b0), "r"(b1));
}

__device__ __forceinline__ void cpasync16(uint32_t smem_addr, const void* gptr) {
    asm volatile("cp.async.cg.shared.global [%0], [%1], 16;"
                 :: "r"(smem_addr), "l"(gptr) : "memory");
}
#define CP_COMMIT()  asm volatile("cp.async.commit_group;" ::: "memory")
#define CP_WAIT(n)   asm volatile("cp.async.wait_group %0;" :: "n"(n) : "memory")

#define LDS128(r0, r1, r2, r3, addr) \
    asm volatile("ld.shared.v4.b32 {%0,%1,%2,%3}, [%4];" \
                 : "=r"(r0), "=r"(r1), "=r"(r2), "=r"(r3) : "r"(addr))

// ------------------- fused stats + LN -> A-fragments, and w -> B-fragments --
// blocks [0, 2048): LN prep for one 16-row mtile (reads x once via SMEM slab)
// blocks [2048, 2176): w fragment conversion (folded in to avoid a serial launch)
static constexpr int XS_STRIDE = 1032;
__global__ void __launch_bounds__(256) prep_kernel(
    const float* __restrict__ x, const float* __restrict__ w,
    const float* __restrict__ gamma, const float* __restrict__ beta) {
    const int tid = threadIdx.x, wr = tid >> 5, lane = tid & 31;

    if (blockIdx.x >= ROWS / 16) {
        // ---------------- w_frag branch (HW-verified layout) ----------------
        const int blk = blockIdx.x - ROWS / 16;       // 0..127
        const int c = blk & 31, nb = blk >> 5;
        const int g = lane >> 2, t = lane & 3;
#pragma unroll
        for (int i = 0; i < 8; i++) {
            const int nt = wr * 4 + (i >> 1);
            const int ksp = i & 1;
            const int n = nb * TN + nt * 8 + g;
            const int kb = c * KC + ksp * 16 + t;
            uint4 o;
            o.x = f2tf32(w[(size_t)kb * D_ + n]);
            o.y = f2tf32(w[(size_t)(kb + 4) * D_ + n]);
            o.z = f2tf32(w[(size_t)(kb + 8) * D_ + n]);
            o.w = f2tf32(w[(size_t)(kb + 12) * D_ + n]);
            reinterpret_cast<uint4*>(g_bfrag)[
                ((size_t)(nb * NCHUNK + c) * 2048) + (nt * 2 + ksp) * 32 + lane] = o;
        }
        return;
    }

    // ------------------------- LN prep branch (unchanged) -------------------
    extern __shared__ float sprep[];
    float* xs = sprep;
    float* sg = sprep + 16 * XS_STRIDE;
    float* sb = sg + 1024;
    __shared__ float smean[16], srstd[16];

    const int blk = blockIdx.x;
    {
        const float4* x4 = reinterpret_cast<const float4*>(x) + (size_t)blk * 16 * 256;
#pragma unroll
        for (int i = 0; i < 16; i++) {
            const int idx = i * 256 + tid;
            const int row = idx >> 8, col4 = idx & 255;
            *reinterpret_cast<float4*>(xs + row * XS_STRIDE + col4 * 4) = x4[row * 256 + col4];
        }
        reinterpret_cast<float4*>(sg)[tid] = reinterpret_cast<const float4*>(gamma)[tid];
        reinterpret_cast<float4*>(sb)[tid] = reinterpret_cast<const float4*>(beta)[tid];
    }
    __syncthreads();

#pragma unroll
    for (int rr = 0; rr < 2; rr++) {
        const int row = wr * 2 + rr;
        float s = 0.f, ss = 0.f;
#pragma unroll
        for (int j = 0; j < 8; j++) {
            const float4 v = *reinterpret_cast<const float4*>(
                xs + row * XS_STRIDE + (lane + j * 32) * 4);
            s  += v.x + v.y + v.z + v.w;
            ss += v.x * v.x + v.y * v.y + v.z * v.z + v.w * v.w;
        }
#pragma unroll
        for (int o = 16; o > 0; o >>= 1) {
            s  += __shfl_xor_sync(0xffffffffu, s, o);
            ss += __shfl_xor_sync(0xffffffffu, ss, o);
        }
        if (lane == 0) {
            const float m = s * (1.0f / N_);
            smean[row] = m;
            srstd[row] = rsqrtf(ss * (1.0f / N_) - m * m + 1e-5f);
        }
    }
    __syncthreads();

    const int g = lane >> 2, t = lane & 3;
    const float mn0 = smean[g],     rs0 = srstd[g];
    const float mn1 = smean[g + 8], rs1 = srstd[g + 8];
    const float* xr0 = xs + g * XS_STRIDE;
    const float* xr1 = xs + (g + 8) * XS_STRIDE;
#pragma unroll
    for (int i = 0; i < 16; i++) {
        const int c  = (i >> 2) * 8 + wr;
        const int ks = i & 3;
        const int k0 = c * KC + ks * 8 + t, k1 = k0 + 4;
        const float ga0 = sg[k0], be0 = sb[k0];
        const float ga1 = sg[k1], be1 = sb[k1];
        uint4 o;
        o.x = f2tf32((xr0[k0] - mn0) * rs0 * ga0 + be0);
        o.y = f2tf32((xr1[k0] - mn1) * rs1 * ga0 + be0);
        o.z = f2tf32((xr0[k1] - mn0) * rs0 * ga1 + be1);
        o.w = f2tf32((xr1[k1] - mn1) * rs1 * ga1 + be1);
        const int rb = blk >> 3, mt = blk & 7;
        reinterpret_cast<uint4*>(g_afrag)[
            (((size_t)(rb * 32 + c) * 32) + mt * 4 + ks) * 32 + lane] = o;
    }
}

// ------------------------------------------------------------- GEMM kernel ---
// CTA 128x256, 8 warps, warp tile 64x64, KC2=64 chunks, 3-stage A cp.async,
// B direct LDG.128 (one-slot lookahead).  NEW: A-fragment LDS are explicitly
// software-pipelined one k8-step ahead (afr double buffer) so the LDS->MMA
// RAW dependency never stalls the MMA issue stream.
__global__ void __launch_bounds__(256, 1) ln_gemm_kernel(
    const float* __restrict__ bias, float* __restrict__ out) {
    extern __shared__ uint32_t smw[];
    const uint32_t sbase = smem_u32(smw);
    const int tid = threadIdx.x, wid = tid >> 5, lane = tid & 31;
    const int bx = blockIdx.x, by = blockIdx.y;
    const int wm = wid >> 2, wn = wid & 3;

    const uint4* gA = reinterpret_cast<const uint4*>(g_afrag) + (size_t)by * NCHUNK * 1024;
    const uint4* gBw = reinterpret_cast<const uint4*>(g_bfrag)
                     + (size_t)bx * NCHUNK * 2048 + (wn * 8) * 2 * 32 + lane;

    // warp-constant part of the A LDS address (mtile i handled by adding i*2048B)
    const uint32_t AwarpBase = sbase + (uint32_t)(wm * 4) * 2048 + (uint32_t)lane * 16;

    auto issueA = [&](int c2, int stage) {
        const uint32_t dstA = sbase + (uint32_t)stage * STAGE_BYTES + tid * 16;
        const uint4* srcA = gA + c2 * 2048 + tid;
#pragma unroll
        for (int i = 0; i < 8; i++) cpasync16(dstA + i * 4096, srcA + i * 256);
        CP_COMMIT();
    };

    auto ldgB = [&](int c, int ksp, uint4* dst) {
        const uint4* p = gBw + (size_t)c * 2048 + ksp * 32;
#pragma unroll
        for (int j = 0; j < 8; j++) dst[j] = p[j * 64];
    };

    // A-fragment LDS for k8-step `step` (0..7) of the chunk whose stage base is Asw
    auto ldsA = [&](uint32_t Asw, int step, uint32_t frag[4][4]) {
        const uint32_t base = AwarpBase + Asw + (uint32_t)step * 512
                            + (uint32_t)(step >> 2) * (16384 - 2048);
        // step 0..3 -> cc=0 at ks*512 ; step 4..7 -> cc=1 (=+16384) at (step-4)*512
        // (step>>2)*(16384-2048): step>=4 adds 16384 and removes the 4*512=2048 overrun
#pragma unroll
        for (int i = 0; i < 4; i++)
            LDS128(frag[i][0], frag[i][1], frag[i][2], frag[i][3], base + (uint32_t)i * 2048);
    };

    issueA(0, 0);
    issueA(1, 1);

    uint4 bX[8], bY[8];
    ldgB(0, 0, bX);

    float acc[4][8][4];
#pragma unroll
    for (int i = 0; i < 4; i++)
#pragma unroll
        for (int j = 0; j < 8; j++)
#pragma unroll
            for (int r = 0; r < 4; r++) acc[i][j][r] = 0.f;

    for (int c2 = 0; c2 < NCH2; c2++) {
        if (c2 < NCH2 - 1) { CP_WAIT(1); } else { CP_WAIT(0); }
        __syncthreads();
        if (c2 + 2 < NCH2) issueA(c2 + 2, (c2 + 2) % NSTAGE);

        const uint32_t Asw = (uint32_t)(c2 % NSTAGE) * STAGE_BYTES;

        // afr pipeline: buffer 0/1 ping-pong over the 8 k8-steps of this chunk
        uint32_t afr[2][4][4];
        ldsA(Asw, 0, afr[0]);

#pragma unroll
        for (int s = 0; s < 4; s++) {
            uint4* cur = (s & 1) ? bY : bX;
            uint4* oth = (s & 1) ? bX : bY;
            if (s < 3)              ldgB(2 * c2 + ((s + 1) >> 1), (s + 1) & 1, oth);
            else if (c2 + 1 < NCH2) ldgB(2 * (c2 + 1), 0, oth);

#pragma unroll
            for (int h = 0; h < 2; h++) {
                const int step = s * 2 + h;
                const int p = step & 1;
                if (step < 7) ldsA(Asw, step + 1, afr[p ^ 1]);   // prefetch next k8
#pragma unroll
                for (int i = 0; i < 4; i++)
#pragma unroll
                    for (int j = 0; j < 8; j++)
                        mma_tf32(acc[i][j], afr[p][i],
                                 h ? cur[j].z : cur[j].x, h ? cur[j].w : cur[j].y);
            }
        }
    }

    // ---- epilogue: acc + bias -> gmem
    const int d0 = bx * TN;
    const int row_base = by * TM;
    const int g = lane >> 2;
    const int t = lane & 3;
    float2 bb[8];
#pragma unroll
    for (int j = 0; j < 8; j++)
        bb[j] = *reinterpret_cast<const float2*>(bias + d0 + wn * 64 + j * 8 + 2 * t);
#pragma unroll
    for (int i = 0; i < 4; i++) {
        const int r0 = row_base + wm * 64 + i * 16 + g;
#pragma unroll
        for (int j = 0; j < 8; j++) {
            const int col = d0 + wn * 64 + j * 8 + 2 * t;
            float2 o0, o1;
            o0.x = acc[i][j][0] + bb[j].x;
            o0.y = acc[i][j][1] + bb[j].y;
            o1.x = acc[i][j][2] + bb[j].x;
            o1.y = acc[i][j][3] + bb[j].y;
            *reinterpret_cast<float2*>(out + (size_t)r0 * D_ + col) = o0;
            *reinterpret_cast<float2*>(out + (size_t)(r0 + 8) * D_ + col) = o1;
        }
    }
}

// ------------------------------------------------------------------ launch ---
extern "C" void kernel_launch(void* const* d_in, const int* in_sizes, int n_in,
                              void* d_out, int out_size) {
    const float* x     = (const float*)d_in[0];
    const float* w     = (const float*)d_in[1];
    const float* b     = (const float*)d_in[2];
    const float* gamma = (const float*)d_in[3];
    const float* beta  = (const float*)d_in[4];
    float* out = (float*)d_out;

    static constexpr int PREP_SMEM = (16 * XS_STRIDE + 2048) * 4;  // 74240 B
    cudaFuncSetAttribute(prep_kernel, cudaFuncAttributeMaxDynamicSharedMemorySize, PREP_SMEM);
    cudaFuncSetAttribute(ln_gemm_kernel, cudaFuncAttributeMaxDynamicSharedMemorySize, SMEM_DYN);

    prep_kernel<<<ROWS / 16 + NCHUNK * NB, 256, PREP_SMEM>>>(x, w, gamma, beta);
    ln_gemm_kernel<<<dim3(NB, RB), 256, SMEM_DYN>>>(b, out);
}

// round 15
// speedup vs baseline: 1.7638x; 1.6693x over previous
#include <cuda_runtime.h>
#include <cuda_fp16.h>
#include <cstdint>

// Problem shape (fixed by reference)
static constexpr int B_ = 8, M_ = 4096, N_ = 1024, D_ = 1024;
static constexpr int ROWS = B_ * M_;            // 32768 LN rows
static constexpr int TM = 128, TN = 256;        // CTA tile
static constexpr int RB = ROWS / TM;            // 256 row blocks
static constexpr int NB = D_ / TN;              // 4 col blocks

// GEMM mainloop K granularity: 64 per chunk, 4 x k16 steps
static constexpr int KC2 = 64;
static constexpr int NCH2 = N_ / KC2;           // 16
static constexpr int NSTAGE = 4;
static constexpr int STAGE_BYTES = TM * KC2 * 2;               // 16384 (fp16)
static constexpr int SMEM_DYN = NSTAGE * STAGE_BYTES;          // 65536

// Device-global fragment scratch (no allocation APIs)
// A fragments (fp16x2 words): [rb 256][c2 16][mt 8][ks16 4][lane 32][4 words]
__device__ uint32_t g_afrag[(size_t)ROWS * N_ / 2];            // 67 MB
// B fragments: [nb 4][c2 16][nt 32][ksp 2][lane 32][4 words]
//   uint4 = { b0(ks16=2p), b1(2p), b0(2p+1), b1(2p+1) }
__device__ uint32_t g_bfrag[(size_t)N_ * D_ / 2];              // 2 MB

// ---------------------------------------------------------------- helpers ---
__device__ __forceinline__ uint32_t f2h2(float lo, float hi) {
    __half2 h = __floats2half2_rn(lo, hi);
    return *reinterpret_cast<uint32_t*>(&h);
}

__device__ __forceinline__ uint32_t smem_u32(const void* p) {
    uint32_t a;
    asm("{ .reg .u64 t; cvta.to.shared.u64 t, %1; cvt.u32.u64 %0, t; }" : "=r"(a) : "l"(p));
    return a;
}

__device__ __forceinline__ void mma_f16(float* c, const uint32_t* a,
                                        uint32_t b0, uint32_t b1) {
    asm volatile(
        "mma.sync.aligned.m16n8k16.row.col.f32.f16.f16.f32 "
        "{%0,%1,%2,%3}, {%4,%5,%6,%7}, {%8,%9}, {%0,%1,%2,%3};"
        : "+f"(c[0]), "+f"(c[1]), "+f"(c[2]), "+f"(c[3])
        : "r"(a[0]), "r"(a[1]), "r"(a[2]), "r"(a[3]), "r"(b0), "r"(b1));
}

__device__ __forceinline__ void cpasync16(uint32_t smem_addr, const void* gptr) {
    asm volatile("cp.async.cg.shared.global [%0], [%1], 16;"
                 :: "r"(smem_addr), "l"(gptr) : "memory");
}
#define CP_COMMIT()  asm volatile("cp.async.commit_group;" ::: "memory")
#define CP_WAIT(n)   asm volatile("cp.async.wait_group %0;" :: "n"(n) : "memory")

#define LDS128(r0, r1, r2, r3, addr) \
    asm volatile("ld.shared.v4.b32 {%0,%1,%2,%3}, [%4];" \
                 : "=r"(r0), "=r"(r1), "=r"(r2), "=r"(r3) : "r"(addr))

// ------------------- fused stats + LN -> A-fragments, and w -> B-fragments --
// blocks [0, 2048): LN prep for one 16-row mtile (reads x once via SMEM slab)
// blocks [2048, 2112): w fragment conversion
// fp16 m16n8k16 fragment maps (PTX spec):
//   A (row-major 16x16): a0=(row g, k 2t|2t+1)  a1=(row g+8, same)
//                        a2=(row g, k 2t+8|2t+9) a3=(row g+8, same)
//   B (col-major 16x8):  b0=(k 2t|2t+1, col g)   b1=(k 2t+8|2t+9, col g)
static constexpr int XS_STRIDE = 1032;
__global__ void __launch_bounds__(256) prep_kernel(
    const float* __restrict__ x, const float* __restrict__ w,
    const float* __restrict__ gamma, const float* __restrict__ beta) {
    const int tid = threadIdx.x, wr = tid >> 5, lane = tid & 31;
    const int g = lane >> 2, t = lane & 3;

    if (blockIdx.x >= ROWS / 16) {
        // ---------------- w_frag branch: one block per (nb, c2) -------------
        const int blk = blockIdx.x - ROWS / 16;       // 0..63
        const int c2 = blk & 15, nb = blk >> 4;
#pragma unroll
        for (int i = 0; i < 8; i++) {
            const int nt = wr * 4 + (i >> 1);
            const int ksp = i & 1;
            const int n = nb * TN + nt * 8 + g;
            const int kA = c2 * 64 + ksp * 32 + 2 * t;       // ks16 = 2*ksp
            const int kB = kA + 16;                           // ks16 = 2*ksp+1
            uint4 o;
            o.x = f2h2(w[(size_t)kA * D_ + n],       w[(size_t)(kA + 1) * D_ + n]);
            o.y = f2h2(w[(size_t)(kA + 8) * D_ + n], w[(size_t)(kA + 9) * D_ + n]);
            o.z = f2h2(w[(size_t)kB * D_ + n],       w[(size_t)(kB + 1) * D_ + n]);
            o.w = f2h2(w[(size_t)(kB + 8) * D_ + n], w[(size_t)(kB + 9) * D_ + n]);
            reinterpret_cast<uint4*>(g_bfrag)[
                ((((size_t)(nb * 16 + c2) * 32 + nt) * 2 + ksp) * 32) + lane] = o;
        }
        return;
    }

    // ------------------------- LN prep branch -------------------------------
    extern __shared__ float sprep[];
    float* xs = sprep;
    float* sg = sprep + 16 * XS_STRIDE;
    float* sb = sg + 1024;
    __shared__ float smean[16], srstd[16];

    const int blk = blockIdx.x;                    // rb = blk>>3, mt = blk&7
    {
        const float4* x4 = reinterpret_cast<const float4*>(x) + (size_t)blk * 16 * 256;
#pragma unroll
        for (int i = 0; i < 16; i++) {
            const int idx = i * 256 + tid;
            const int row = idx >> 8, col4 = idx & 255;
            *reinterpret_cast<float4*>(xs + row * XS_STRIDE + col4 * 4) = x4[row * 256 + col4];
        }
        reinterpret_cast<float4*>(sg)[tid] = reinterpret_cast<const float4*>(gamma)[tid];
        reinterpret_cast<float4*>(sb)[tid] = reinterpret_cast<const float4*>(beta)[tid];
    }
    __syncthreads();

#pragma unroll
    for (int rr = 0; rr < 2; rr++) {
        const int row = wr * 2 + rr;
        float s = 0.f, ss = 0.f;
#pragma unroll
        for (int j = 0; j < 8; j++) {
            const float4 v = *reinterpret_cast<const float4*>(
                xs + row * XS_STRIDE + (lane + j * 32) * 4);
            s  += v.x + v.y + v.z + v.w;
            ss += v.x * v.x + v.y * v.y + v.z * v.z + v.w * v.w;
        }
#pragma unroll
        for (int o = 16; o > 0; o >>= 1) {
            s  += __shfl_xor_sync(0xffffffffu, s, o);
            ss += __shfl_xor_sync(0xffffffffu, ss, o);
        }
        if (lane == 0) {
            const float m = s * (1.0f / N_);
            smean[row] = m;
            srstd[row] = rsqrtf(ss * (1.0f / N_) - m * m + 1e-5f);
        }
    }
    __syncthreads();

    const float mn0 = smean[g],     rs0 = srstd[g];
    const float mn1 = smean[g + 8], rs1 = srstd[g + 8];
    const float* xr0 = xs + g * XS_STRIDE;
    const float* xr1 = xs + (g + 8) * XS_STRIDE;
    const int rb = blk >> 3, mt = blk & 7;

    // 64 (c2, ks16) combos, 8 per warp
#pragma unroll
    for (int i = 0; i < 8; i++) {
        const int combo = wr * 8 + i;
        const int c2 = combo >> 2, ks16 = combo & 3;
        const int k0 = c2 * 64 + ks16 * 16 + 2 * t;   // pair (k0, k0+1)
        const int k2 = k0 + 8;                         // pair (k2, k2+1)
        // LN in fp32, round once to fp16
        const float l00 = (xr0[k0]     - mn0) * rs0 * sg[k0]     + sb[k0];
        const float l01 = (xr0[k0 + 1] - mn0) * rs0 * sg[k0 + 1] + sb[k0 + 1];
        const float l10 = (xr1[k0]     - mn1) * rs1 * sg[k0]     + sb[k0];
        const float l11 = (xr1[k0 + 1] - mn1) * rs1 * sg[k0 + 1] + sb[k0 + 1];
        const float l20 = (xr0[k2]     - mn0) * rs0 * sg[k2]     + sb[k2];
        const float l21 = (xr0[k2 + 1] - mn0) * rs0 * sg[k2 + 1] + sb[k2 + 1];
        const float l30 = (xr1[k2]     - mn1) * rs1 * sg[k2]     + sb[k2];
        const float l31 = (xr1[k2 + 1] - mn1) * rs1 * sg[k2 + 1] + sb[k2 + 1];
        uint4 o;
        o.x = f2h2(l00, l01);   // a0
        o.y = f2h2(l10, l11);   // a1
        o.z = f2h2(l20, l21);   // a2
        o.w = f2h2(l30, l31);   // a3
        // [rb][c2][mt][ks16][lane] in uint4 units
        reinterpret_cast<uint4*>(g_afrag)[
            (((size_t)(rb * 16 + c2) * 8 + mt) * 4 + ks16) * 32 + lane] = o;
    }
}

// ------------------------------------------------------------- GEMM kernel ---
// CTA 128x256, 8 warps, warp tile 64x64, fp16 m16n8k16 MMAs.
// A via 4-stage cp.async (16KB/chunk); B direct LDG.128 from L2 with
// register ping-pong; A-fragment LDS pipelined one k16-step ahead.
__global__ void __launch_bounds__(256, 1) ln_gemm_kernel(
    const float* __restrict__ bias, float* __restrict__ out) {
    extern __shared__ uint32_t smw[];
    const uint32_t sbase = smem_u32(smw);
    const int tid = threadIdx.x, wid = tid >> 5, lane = tid & 31;
    const int bx = blockIdx.x, by = blockIdx.y;
    const int wm = wid >> 2, wn = wid & 3;

    // A: per (rb, c2): 8 mt x 4 ks16 x 32 lanes = 1024 uint4 (16 KB)
    const uint4* gA = reinterpret_cast<const uint4*>(g_afrag) + (size_t)by * NCH2 * 1024;
    // B: per (nb, c2): 32 nt x 2 ksp x 32 lanes = 2048 uint4 (32 KB)
    const uint4* gBw = reinterpret_cast<const uint4*>(g_bfrag)
                     + (size_t)bx * NCH2 * 2048 + (size_t)(wn * 8) * 64 + lane;

    // warp-constant A LDS base: mtile (wm*4+i) at +i*2048B, step at +step*512B
    const uint32_t AwarpBase = sbase + (uint32_t)(wm * 4) * 2048 + (uint32_t)lane * 16;

    auto issueA = [&](int c2, int stage) {
        const uint32_t dstA = sbase + (uint32_t)stage * STAGE_BYTES + tid * 16;
        const uint4* srcA = gA + c2 * 1024 + tid;
#pragma unroll
        for (int i = 0; i < 4; i++) cpasync16(dstA + i * 4096, srcA + i * 256);
        CP_COMMIT();
    };

    // this warp's 8 B-fragment uint4s for (chunk c2, ksp)
    auto ldgB = [&](int c2, int ksp, uint4* dst) {
        const uint4* p = gBw + (size_t)c2 * 2048 + ksp * 32;
#pragma unroll
        for (int j = 0; j < 8; j++) dst[j] = p[j * 64];
    };

    auto ldsA = [&](uint32_t Asw, int step, uint32_t frag[4][4]) {
        const uint32_t base = AwarpBase + Asw + (uint32_t)step * 512;
#pragma unroll
        for (int i = 0; i < 4; i++)
            LDS128(frag[i][0], frag[i][1], frag[i][2], frag[i][3], base + (uint32_t)i * 2048);
    };

    issueA(0, 0);
    issueA(1, 1);
    issueA(2, 2);

    uint4 bX[8], bY[8];
    ldgB(0, 0, bX);

    float acc[4][8][4];
#pragma unroll
    for (int i = 0; i < 4; i++)
#pragma unroll
        for (int j = 0; j < 8; j++)
#pragma unroll
            for (int r = 0; r < 4; r++) acc[i][j][r] = 0.f;

    for (int c2 = 0; c2 < NCH2; c2++) {
        if (c2 < NCH2 - 2)       { CP_WAIT(2); }
        else if (c2 == NCH2 - 2) { CP_WAIT(1); }
        else                     { CP_WAIT(0); }
        __syncthreads();
        if (c2 + 3 < NCH2) issueA(c2 + 3, (c2 + 3) & 3);

        const uint32_t Asw = (uint32_t)(c2 & 3) * STAGE_BYTES;

        uint32_t afr[2][4][4];
        ldsA(Asw, 0, afr[0]);

#pragma unroll
        for (int s = 0; s < 2; s++) {                 // ksp slots
            uint4* cur = s ? bY : bX;
            uint4* oth = s ? bX : bY;
            if (s == 0)             ldgB(c2, 1, oth);
            else if (c2 + 1 < NCH2) ldgB(c2 + 1, 0, oth);

#pragma unroll
            for (int h = 0; h < 2; h++) {             // ks16 within slot
                const int step = s * 2 + h;
                const int p = step & 1;
                if (step < 3) ldsA(Asw, step + 1, afr[p ^ 1]);
#pragma unroll
                for (int i = 0; i < 4; i++)
#pragma unroll
                    for (int j = 0; j < 8; j++)
                        mma_f16(acc[i][j], afr[p][i],
                                h ? cur[j].z : cur[j].x, h ? cur[j].w : cur[j].y);
            }
        }
    }

    // ---- epilogue: acc + bias -> gmem (C mapping identical to tf32 path)
    const int d0 = bx * TN;
    const int row_base = by * TM;
    const int g = lane >> 2;
    const int t = lane & 3;
    float2 bb[8];
#pragma unroll
    for (int j = 0; j < 8; j++)
        bb[j] = *reinterpret_cast<const float2*>(bias + d0 + wn * 64 + j * 8 + 2 * t);
#pragma unroll
    for (int i = 0; i < 4; i++) {
        const int r0 = row_base + wm * 64 + i * 16 + g;
#pragma unroll
        for (int j = 0; j < 8; j++) {
            const int col = d0 + wn * 64 + j * 8 + 2 * t;
            float2 o0, o1;
            o0.x = acc[i][j][0] + bb[j].x;
            o0.y = acc[i][j][1] + bb[j].y;
            o1.x = acc[i][j][2] + bb[j].x;
            o1.y = acc[i][j][3] + bb[j].y;
            *reinterpret_cast<float2*>(out + (size_t)r0 * D_ + col) = o0;
            *reinterpret_cast<float2*>(out + (size_t)(r0 + 8) * D_ + col) = o1;
        }
    }
}

// ------------------------------------------------------------------ launch ---
extern "C" void kernel_launch(void* const* d_in, const int* in_sizes, int n_in,
                              void* d_out, int out_size) {
    const float* x     = (const float*)d_in[0];
    const float* w     = (const float*)d_in[1];
    const float* b     = (const float*)d_in[2];
    const float* gamma = (const float*)d_in[3];
    const float* beta  = (const float*)d_in[4];
    float* out = (float*)d_out;

    static constexpr int PREP_SMEM = (16 * XS_STRIDE + 2048) * 4;  // 74240 B
    cudaFuncSetAttribute(prep_kernel, cudaFuncAttributeMaxDynamicSharedMemorySize, PREP_SMEM);
    cudaFuncSetAttribute(ln_gemm_kernel, cudaFuncAttributeMaxDynamicSharedMemorySize, SMEM_DYN);

    prep_kernel<<<ROWS / 16 + NB * NCH2, 256, PREP_SMEM>>>(x, w, gamma, beta);
    ln_gemm_kernel<<<dim3(NB, RB), 256, SMEM_DYN>>>(b, out);
}

// round 16
// speedup vs baseline: 1.7661x; 1.0013x over previous
#include <cuda_runtime.h>
#include <cuda_fp16.h>
#include <cstdint>

// Problem shape (fixed by reference)
static constexpr int B_ = 8, M_ = 4096, N_ = 1024, D_ = 1024;
static constexpr int ROWS = B_ * M_;            // 32768 LN rows
static constexpr int TM = 128, TN = 256;        // CTA tile
static constexpr int RB = ROWS / TM;            // 256 row blocks
static constexpr int NB = D_ / TN;              // 4 col blocks

// GEMM mainloop K granularity: 64 per chunk, 4 x k16 steps
static constexpr int KC2 = 64;
static constexpr int NCH2 = N_ / KC2;           // 16
static constexpr int NSTAGE = 4;
static constexpr int STAGE_BYTES = TM * KC2 * 2;               // 16384 (fp16)
static constexpr int SMEM_DYN = NSTAGE * STAGE_BYTES;          // 65536

// Device-global fragment scratch (no allocation APIs)
// A fragments (fp16x2 words): [rb 256][c2 16][mt 8][ks16 4][lane 32][4 words]
__device__ uint32_t g_afrag[(size_t)ROWS * N_ / 2];            // 67 MB
// B fragments: [nb 4][c2 16][nt 32][ksp 2][lane 32][4 words]
//   uint4 = { b0(ks16=2p), b1(2p), b0(2p+1), b1(2p+1) }
__device__ uint32_t g_bfrag[(size_t)N_ * D_ / 2];              // 2 MB

// ---------------------------------------------------------------- helpers ---
__device__ __forceinline__ uint32_t f2h2(float lo, float hi) {
    __half2 h = __floats2half2_rn(lo, hi);
    return *reinterpret_cast<uint32_t*>(&h);
}

__device__ __forceinline__ uint32_t smem_u32(const void* p) {
    uint32_t a;
    asm("{ .reg .u64 t; cvta.to.shared.u64 t, %1; cvt.u32.u64 %0, t; }" : "=r"(a) : "l"(p));
    return a;
}

__device__ __forceinline__ void mma_f16(float* c, const uint32_t* a,
                                        uint32_t b0, uint32_t b1) {
    asm volatile(
        "mma.sync.aligned.m16n8k16.row.col.f32.f16.f16.f32 "
        "{%0,%1,%2,%3}, {%4,%5,%6,%7}, {%8,%9}, {%0,%1,%2,%3};"
        : "+f"(c[0]), "+f"(c[1]), "+f"(c[2]), "+f"(c[3])
        : "r"(a[0]), "r"(a[1]), "r"(a[2]), "r"(a[3]), "r"(b0), "r"(b1));
}

__device__ __forceinline__ void cpasync16(uint32_t smem_addr, const void* gptr) {
    asm volatile("cp.async.cg.shared.global [%0], [%1], 16;"
                 :: "r"(smem_addr), "l"(gptr) : "memory");
}
#define CP_COMMIT()  asm volatile("cp.async.commit_group;" ::: "memory")
#define CP_WAIT(n)   asm volatile("cp.async.wait_group %0;" :: "n"(n) : "memory")

#define LDS128(r0, r1, r2, r3, addr) \
    asm volatile("ld.shared.v4.b32 {%0,%1,%2,%3}, [%4];" \
                 : "=r"(r0), "=r"(r1), "=r"(r2), "=r"(r3) : "r"(addr))

// ------------------- fused stats + LN -> A-fragments, and w -> B-fragments --
// blocks [0, 2048): LN prep for one 16-row mtile (reads x once via SMEM slab)
// blocks [2048, 2112): w fragment conversion
// fp16 m16n8k16 fragment maps (PTX spec):
//   A (row-major 16x16): a0=(row g, k 2t|2t+1)  a1=(row g+8, same)
//                        a2=(row g, k 2t+8|2t+9) a3=(row g+8, same)
//   B (col-major 16x8):  b0=(k 2t|2t+1, col g)   b1=(k 2t+8|2t+9, col g)
static constexpr int XS_STRIDE = 1032;
__global__ void __launch_bounds__(256) prep_kernel(
    const float* __restrict__ x, const float* __restrict__ w,
    const float* __restrict__ gamma, const float* __restrict__ beta) {
    const int tid = threadIdx.x, wr = tid >> 5, lane = tid & 31;
    const int g = lane >> 2, t = lane & 3;

    if (blockIdx.x >= ROWS / 16) {
        // ---------------- w_frag branch: one block per (nb, c2) -------------
        const int blk = blockIdx.x - ROWS / 16;       // 0..63
        const int c2 = blk & 15, nb = blk >> 4;
#pragma unroll
        for (int i = 0; i < 8; i++) {
            const int nt = wr * 4 + (i >> 1);
            const int ksp = i & 1;
            const int n = nb * TN + nt * 8 + g;
            const int kA = c2 * 64 + ksp * 32 + 2 * t;       // ks16 = 2*ksp
            const int kB = kA + 16;                           // ks16 = 2*ksp+1
            uint4 o;
            o.x = f2h2(w[(size_t)kA * D_ + n],       w[(size_t)(kA + 1) * D_ + n]);
            o.y = f2h2(w[(size_t)(kA + 8) * D_ + n], w[(size_t)(kA + 9) * D_ + n]);
            o.z = f2h2(w[(size_t)kB * D_ + n],       w[(size_t)(kB + 1) * D_ + n]);
            o.w = f2h2(w[(size_t)(kB + 8) * D_ + n], w[(size_t)(kB + 9) * D_ + n]);
            reinterpret_cast<uint4*>(g_bfrag)[
                ((((size_t)(nb * 16 + c2) * 32 + nt) * 2 + ksp) * 32) + lane] = o;
        }
        return;
    }

    // ------------------------- LN prep branch -------------------------------
    extern __shared__ float sprep[];
    float* xs = sprep;
    float* sg = sprep + 16 * XS_STRIDE;
    float* sb = sg + 1024;
    __shared__ float smean[16], srstd[16];

    const int blk = blockIdx.x;                    // rb = blk>>3, mt = blk&7
    {
        const float4* x4 = reinterpret_cast<const float4*>(x) + (size_t)blk * 16 * 256;
#pragma unroll
        for (int i = 0; i < 16; i++) {
            const int idx = i * 256 + tid;
            const int row = idx >> 8, col4 = idx & 255;
            *reinterpret_cast<float4*>(xs + row * XS_STRIDE + col4 * 4) = x4[row * 256 + col4];
        }
        reinterpret_cast<float4*>(sg)[tid] = reinterpret_cast<const float4*>(gamma)[tid];
        reinterpret_cast<float4*>(sb)[tid] = reinterpret_cast<const float4*>(beta)[tid];
    }
    __syncthreads();

#pragma unroll
    for (int rr = 0; rr < 2; rr++) {
        const int row = wr * 2 + rr;
        float s = 0.f, ss = 0.f;
#pragma unroll
        for (int j = 0; j < 8; j++) {
            const float4 v = *reinterpret_cast<const float4*>(
                xs + row * XS_STRIDE + (lane + j * 32) * 4);
            s  += v.x + v.y + v.z + v.w;
            ss += v.x * v.x + v.y * v.y + v.z * v.z + v.w * v.w;
        }
#pragma unroll
        for (int o = 16; o > 0; o >>= 1) {
            s  += __shfl_xor_sync(0xffffffffu, s, o);
            ss += __shfl_xor_sync(0xffffffffu, ss, o);
        }
        if (lane == 0) {
            const float m = s * (1.0f / N_);
            smean[row] = m;
            srstd[row] = rsqrtf(ss * (1.0f / N_) - m * m + 1e-5f);
        }
    }
    __syncthreads();

    const float mn0 = smean[g],     rs0 = srstd[g];
    const float mn1 = smean[g + 8], rs1 = srstd[g + 8];
    const float* xr0 = xs + g * XS_STRIDE;
    const float* xr1 = xs + (g + 8) * XS_STRIDE;
    const int rb = blk >> 3, mt = blk & 7;

    // 64 (c2, ks16) combos, 8 per warp
#pragma unroll
    for (int i = 0; i < 8; i++) {
        const int combo = wr * 8 + i;
        const int c2 = combo >> 2, ks16 = combo & 3;
        const int k0 = c2 * 64 + ks16 * 16 + 2 * t;   // pair (k0, k0+1)
        const int k2 = k0 + 8;                         // pair (k2, k2+1)
        // LN in fp32, round once to fp16
        const float l00 = (xr0[k0]     - mn0) * rs0 * sg[k0]     + sb[k0];
        const float l01 = (xr0[k0 + 1] - mn0) * rs0 * sg[k0 + 1] + sb[k0 + 1];
        const float l10 = (xr1[k0]     - mn1) * rs1 * sg[k0]     + sb[k0];
        const float l11 = (xr1[k0 + 1] - mn1) * rs1 * sg[k0 + 1] + sb[k0 + 1];
        const float l20 = (xr0[k2]     - mn0) * rs0 * sg[k2]     + sb[k2];
        const float l21 = (xr0[k2 + 1] - mn0) * rs0 * sg[k2 + 1] + sb[k2 + 1];
        const float l30 = (xr1[k2]     - mn1) * rs1 * sg[k2]     + sb[k2];
        const float l31 = (xr1[k2 + 1] - mn1) * rs1 * sg[k2 + 1] + sb[k2 + 1];
        uint4 o;
        o.x = f2h2(l00, l01);   // a0
        o.y = f2h2(l10, l11);   // a1
        o.z = f2h2(l20, l21);   // a2
        o.w = f2h2(l30, l31);   // a3
        // [rb][c2][mt][ks16][lane] in uint4 units
        reinterpret_cast<uint4*>(g_afrag)[
            (((size_t)(rb * 16 + c2) * 8 + mt) * 4 + ks16) * 32 + lane] = o;
    }
}

// ------------------------------------------------------------- GEMM kernel ---
// CTA 128x256, 8 warps, warp tile 64x64, fp16 m16n8k16 MMAs.
// A via 4-stage cp.async (16KB/chunk); B direct LDG.128 from L2 with
// register ping-pong; A-fragment LDS pipelined one k16-step ahead.
__global__ void __launch_bounds__(256, 1) ln_gemm_kernel(
    const float* __restrict__ bias, float* __restrict__ out) {
    extern __shared__ uint32_t smw[];
    const uint32_t sbase = smem_u32(smw);
    const int tid = threadIdx.x, wid = tid >> 5, lane = tid & 31;
    const int bx = blockIdx.x, by = blockIdx.y;
    const int wm = wid >> 2, wn = wid & 3;

    // A: per (rb, c2): 8 mt x 4 ks16 x 32 lanes = 1024 uint4 (16 KB)
    const uint4* gA = reinterpret_cast<const uint4*>(g_afrag) + (size_t)by * NCH2 * 1024;
    // B: per (nb, c2): 32 nt x 2 ksp x 32 lanes = 2048 uint4 (32 KB)
    const uint4* gBw = reinterpret_cast<const uint4*>(g_bfrag)
                     + (size_t)bx * NCH2 * 2048 + (size_t)(wn * 8) * 64 + lane;

    // warp-constant A LDS base: mtile (wm*4+i) at +i*2048B, step at +step*512B
    const uint32_t AwarpBase = sbase + (uint32_t)(wm * 4) * 2048 + (uint32_t)lane * 16;

    auto issueA = [&](int c2, int stage) {
        const uint32_t dstA = sbase + (uint32_t)stage * STAGE_BYTES + tid * 16;
        const uint4* srcA = gA + c2 * 1024 + tid;
#pragma unroll
        for (int i = 0; i < 4; i++) cpasync16(dstA + i * 4096, srcA + i * 256);
        CP_COMMIT();
    };

    // this warp's 8 B-fragment uint4s for (chunk c2, ksp)
    auto ldgB = [&](int c2, int ksp, uint4* dst) {
        const uint4* p = gBw + (size_t)c2 * 2048 + ksp * 32;
#pragma unroll
        for (int j = 0; j < 8; j++) dst[j] = p[j * 64];
    };

    auto ldsA = [&](uint32_t Asw, int step, uint32_t frag[4][4]) {
        const uint32_t base = AwarpBase + Asw + (uint32_t)step * 512;
#pragma unroll
        for (int i = 0; i < 4; i++)
            LDS128(frag[i][0], frag[i][1], frag[i][2], frag[i][3], base + (uint32_t)i * 2048);
    };

    issueA(0, 0);
    issueA(1, 1);
    issueA(2, 2);

    uint4 bX[8], bY[8];
    ldgB(0, 0, bX);

    float acc[4][8][4];
#pragma unroll
    for (int i = 0; i < 4; i++)
#pragma unroll
        for (int j = 0; j < 8; j++)
#pragma unroll
            for (int r = 0; r < 4; r++) acc[i][j][r] = 0.f;

    for (int c2 = 0; c2 < NCH2; c2++) {
        if (c2 < NCH2 - 2)       { CP_WAIT(2); }
        else if (c2 == NCH2 - 2) { CP_WAIT(1); }
        else                     { CP_WAIT(0); }
        __syncthreads();
        if (c2 + 3 < NCH2) issueA(c2 + 3, (c2 + 3) & 3);

        const uint32_t Asw = (uint32_t)(c2 & 3) * STAGE_BYTES;

        uint32_t afr[2][4][4];
        ldsA(Asw, 0, afr[0]);

#pragma unroll
        for (int s = 0; s < 2; s++) {                 // ksp slots
            uint4* cur = s ? bY : bX;
            uint4* oth = s ? bX : bY;
            if (s == 0)             ldgB(c2, 1, oth);
            else if (c2 + 1 < NCH2) ldgB(c2 + 1, 0, oth);

#pragma unroll
            for (int h = 0; h < 2; h++) {             // ks16 within slot
                const int step = s * 2 + h;
                const int p = step & 1;
                if (step < 3) ldsA(Asw, step + 1, afr[p ^ 1]);
#pragma unroll
                for (int i = 0; i < 4; i++)
#pragma unroll
                    for (int j = 0; j < 8; j++)
                        mma_f16(acc[i][j], afr[p][i],
                                h ? cur[j].z : cur[j].x, h ? cur[j].w : cur[j].y);
            }
        }
    }

    // ---- epilogue: acc + bias -> gmem (C mapping identical to tf32 path)
    const int d0 = bx * TN;
    const int row_base = by * TM;
    const int g = lane >> 2;
    const int t = lane & 3;
    float2 bb[8];
#pragma unroll
    for (int j = 0; j < 8; j++)
        bb[j] = *reinterpret_cast<const float2*>(bias + d0 + wn * 64 + j * 8 + 2 * t);
#pragma unroll
    for (int i = 0; i < 4; i++) {
        const int r0 = row_base + wm * 64 + i * 16 + g;
#pragma unroll
        for (int j = 0; j < 8; j++) {
            const int col = d0 + wn * 64 + j * 8 + 2 * t;
            float2 o0, o1;
            o0.x = acc[i][j][0] + bb[j].x;
            o0.y = acc[i][j][1] + bb[j].y;
            o1.x = acc[i][j][2] + bb[j].x;
            o1.y = acc[i][j][3] + bb[j].y;
            *reinterpret_cast<float2*>(out + (size_t)r0 * D_ + col) = o0;
            *reinterpret_cast<float2*>(out + (size_t)(r0 + 8) * D_ + col) = o1;
        }
    }
}

// ------------------------------------------------------------------ launch ---
extern "C" void kernel_launch(void* const* d_in, const int* in_sizes, int n_in,
                              void* d_out, int out_size) {
    const float* x     = (const float*)d_in[0];
    const float* w     = (const float*)d_in[1];
    const float* b     = (const float*)d_in[2];
    const float* gamma = (const float*)d_in[3];
    const float* beta  = (const float*)d_in[4];
    float* out = (float*)d_out;

    static constexpr int PREP_SMEM = (16 * XS_STRIDE + 2048) * 4;  // 74240 B
    cudaFuncSetAttribute(prep_kernel, cudaFuncAttributeMaxDynamicSharedMemorySize, PREP_SMEM);
    cudaFuncSetAttribute(ln_gemm_kernel, cudaFuncAttributeMaxDynamicSharedMemorySize, SMEM_DYN);

    prep_kernel<<<ROWS / 16 + NB * NCH2, 256, PREP_SMEM>>>(x, w, gamma, beta);
    ln_gemm_kernel<<<dim3(NB, RB), 256, SMEM_DYN>>>(b, out);
}